// round 3
// baseline (speedup 1.0000x reference)
#include <cuda_runtime.h>
#include <cstdint>

#define NC        100000
#define FEAT      256
#define BATCH     16384
#define F4        64                    // FEAT / 4
#define THREADS   256
#define WPB       8                     // warps per block
#define ACC_BLOCKS (BATCH / WPB)        // 2048: one warp per sample
#define NSHARD    32
#define SHARD_CAP 1024                  // ~472 expected per shard; 1024 = +26 sigma
#define CLS_BLOCKS ((NSHARD * SHARD_CAP) / WPB)   // 4096: one warp per list slot

// Scratch. All-zero at module load; every replay restores the all-zero invariant.
__device__ float4   g_sums[(size_t)NC * F4];     // per-class feature sums (~102 MB)
__device__ float    g_q[NC];                     // per-class sum of ||x_i||^2
__device__ int      g_counts[NC];
__device__ int      g_nt[NSHARD];                // sharded touched-class counters
__device__ int      g_list[NSHARD][SHARD_CAP];   // touched-class lists
__device__ float    g_partials[CLS_BLOCKS];
__device__ unsigned g_done;

__device__ __forceinline__ void red_add_v4(float* addr, float4 v) {
    asm volatile("red.global.add.v4.f32 [%0], {%1, %2, %3, %4};"
                 :: "l"(addr), "f"(v.x), "f"(v.y), "f"(v.z), "f"(v.w)
                 : "memory");
}

// ---------------------------------------------------------------------------
// Pass 1: one warp per sample. Scatter-add feature row and ||x||^2 into the
// (zero-by-invariant) class accumulators; first arrival per class pushes it
// onto a sharded touched list.
// ---------------------------------------------------------------------------
__global__ __launch_bounds__(THREADS) void accum(const float* __restrict__ x,
                                                 const int* __restrict__ label) {
    int w    = (blockIdx.x * THREADS + threadIdx.x) >> 5;   // sample id
    int lane = threadIdx.x & 31;
    int c    = label[w];

    const float4* xr = reinterpret_cast<const float4*>(x) + (size_t)w * F4;
    float4 v0 = xr[lane];
    float4 v1 = xr[lane + 32];

    float* srow = reinterpret_cast<float*>(g_sums + (size_t)c * F4);
    red_add_v4(srow + lane * 4,        v0);
    red_add_v4(srow + (lane + 32) * 4, v1);

    float q = v0.x*v0.x + v0.y*v0.y + v0.z*v0.z + v0.w*v0.w
            + v1.x*v1.x + v1.y*v1.y + v1.z*v1.z + v1.w*v1.w;
    #pragma unroll
    for (int o = 16; o > 0; o >>= 1)
        q += __shfl_down_sync(0xFFFFFFFFu, q, o);

    if (lane == 0) {
        atomicAdd(&g_q[c], q);
        if (atomicAdd(&g_counts[c], 1) == 0) {
            int sh  = c & (NSHARD - 1);
            int pos = atomicAdd(&g_nt[sh], 1);
            if (pos < SHARD_CAP) g_list[sh][pos] = c;
        }
    }
}

// ---------------------------------------------------------------------------
// Pass 2: one warp per touched class.
//   contrib_c = Q_c - 2 t.s + n ||t||^2,  t = 0.99 c + (0.01/n) s
// Re-zeroes all touched scratch (restores invariant). Last block reduces the
// per-block partials, writes the loss, and resets the counters.
// ---------------------------------------------------------------------------
__global__ __launch_bounds__(THREADS) void classpass(const float* __restrict__ center,
                                                     float* __restrict__ out) {
    int w     = (blockIdx.x * THREADS + threadIdx.x) >> 5;
    int lane  = threadIdx.x & 31;
    int shard = w >> 10;                 // w / SHARD_CAP
    int idx   = w & (SHARD_CAP - 1);

    float contrib = 0.f;
    if (idx < g_nt[shard]) {
        int c = g_list[shard][idx];
        float n  = (float)g_counts[c];
        float bn = 0.01f / n;

        float4*       srow = g_sums + (size_t)c * F4;
        const float4* crow = reinterpret_cast<const float4*>(center) + (size_t)c * F4;

        float4 s0 = srow[lane], s1 = srow[lane + 32];
        float4 c0 = crow[lane], c1 = crow[lane + 32];

        // restore zero invariant
        float4 z = make_float4(0.f, 0.f, 0.f, 0.f);
        srow[lane] = z;
        srow[lane + 32] = z;

        #define TERM(cj, sj) { float t = 0.99f * (cj) + bn * (sj); \
                               contrib += fmaf(n * t, t, -2.f * t * (sj)); }
        TERM(c0.x, s0.x) TERM(c0.y, s0.y) TERM(c0.z, s0.z) TERM(c0.w, s0.w)
        TERM(c1.x, s1.x) TERM(c1.y, s1.y) TERM(c1.z, s1.z) TERM(c1.w, s1.w)
        #undef TERM

        if (lane == 0) {
            contrib += g_q[c];
            g_q[c] = 0.f;           // restore invariants
            g_counts[c] = 0;
        }
    }

    #pragma unroll
    for (int o = 16; o > 0; o >>= 1)
        contrib += __shfl_down_sync(0xFFFFFFFFu, contrib, o);

    __shared__ float sh[WPB];
    __shared__ bool  isLast;
    if (lane == 0) sh[threadIdx.x >> 5] = contrib;
    __syncthreads();

    if (threadIdx.x == 0) {
        float b = 0.f;
        #pragma unroll
        for (int i = 0; i < WPB; i++) b += sh[i];
        g_partials[blockIdx.x] = b;
        __threadfence();
        unsigned t = atomicAdd(&g_done, 1u);
        isLast = (t == (unsigned)(gridDim.x - 1));
    }
    __syncthreads();

    if (isLast) {
        // final deterministic-order reduce of the partials (L2 loads: other
        // SMs wrote them; this block never cached them in L1)
        float a = 0.f;
        for (int i = threadIdx.x; i < CLS_BLOCKS; i += THREADS)
            a += __ldcg(&g_partials[i]);
        __shared__ float fin[THREADS];
        fin[threadIdx.x] = a;
        __syncthreads();
        #pragma unroll
        for (int o = THREADS / 2; o > 0; o >>= 1) {
            if (threadIdx.x < o) fin[threadIdx.x] += fin[threadIdx.x + o];
            __syncthreads();
        }
        if (threadIdx.x < NSHARD) g_nt[threadIdx.x] = 0;   // reset counters
        if (threadIdx.x == 0) {
            g_done = 0u;
            out[0] = fin[0] * (1.f / ((float)BATCH * (float)FEAT));
        }
    }
}

extern "C" void kernel_launch(void* const* d_in, const int* in_sizes, int n_in,
                              void* d_out, int out_size) {
    const float* x      = (const float*)d_in[0];   // batch_feature [16384, 256] f32
    const int*   label  = (const int*)d_in[1];     // batch_label   [16384] int32
    const float* center = (const float*)d_in[2];   // center_feature[100000, 256] f32
    float* out = (float*)d_out;

    accum    <<<ACC_BLOCKS, THREADS>>>(x, label);
    classpass<<<CLS_BLOCKS, THREADS>>>(center, out);
}

// round 4
// speedup vs baseline: 1.3830x; 1.3830x over previous
#include <cuda_runtime.h>
#include <cstdint>

#define NC         100000
#define FEAT       256
#define BATCH      16384
#define F4         64                          // FEAT / 4
#define THREADS    256
#define WPB        8                           // warps per block
#define ACC_BLOCKS (BATCH / WPB)               // 2048 (one warp per sample)
#define CPB        256                         // classes scanned per block
#define CLS_BLOCKS ((NC + CPB - 1) / CPB)      // 391
#define PARTIALS   512                         // >= CLS_BLOCKS

// Scratch — zero at module load; every launch restores the all-zero invariant,
// so no zeroing pass is ever needed.
__device__ float4 g_sums[(size_t)NC * F4];     // per-class feature sums (~102 MB)
__device__ float  g_q[NC];                     // per-class sum of ||x_i||^2
__device__ int    g_counts[NC];
__device__ float  g_partials[PARTIALS];

__device__ __forceinline__ void red_add_v4(float* addr, float4 v) {
    asm volatile("red.global.add.v4.f32 [%0], {%1, %2, %3, %4};"
                 :: "l"(addr), "f"(v.x), "f"(v.y), "f"(v.z), "f"(v.w)
                 : "memory");
}

// ---------------------------------------------------------------------------
// Pass 1: one warp per sample. Scatter-add the feature row (vector RED) and
// ||x||^2 + count (no-return atomics, spread over ~15.5K addresses).
// ---------------------------------------------------------------------------
__global__ __launch_bounds__(THREADS) void accum(const float* __restrict__ x,
                                                 const int* __restrict__ label) {
    int w    = (blockIdx.x * THREADS + threadIdx.x) >> 5;   // sample id
    int lane = threadIdx.x & 31;
    int c    = label[w];                                    // broadcast load

    const float4* xr = reinterpret_cast<const float4*>(x) + (size_t)w * F4;
    float4 v0 = xr[lane];
    float4 v1 = xr[lane + 32];

    float* srow = reinterpret_cast<float*>(g_sums + (size_t)c * F4);
    red_add_v4(srow + lane * 4,        v0);
    red_add_v4(srow + (lane + 32) * 4, v1);

    float q = v0.x*v0.x + v0.y*v0.y + v0.z*v0.z + v0.w*v0.w
            + v1.x*v1.x + v1.y*v1.y + v1.z*v1.z + v1.w*v1.w;
    #pragma unroll
    for (int o = 16; o > 0; o >>= 1)
        q += __shfl_down_sync(0xFFFFFFFFu, q, o);

    if (lane == 0) {
        atomicAdd(&g_q[c], q);        // no-return -> REDG, spread addresses
        atomicAdd(&g_counts[c], 1);
    }
}

// ---------------------------------------------------------------------------
// Pass 2: block scans 256 classes' counts (coalesced), compacts touched ones
// into smem, then warps compute per-class contributions:
//   contrib_c = Q_c - 2 t.s + n ||t||^2,   t = 0.99 c + (0.01/n) s
// and restore the zero invariant on all touched scratch. Block partial ->
// g_partials (no global atomics anywhere).
// ---------------------------------------------------------------------------
__global__ __launch_bounds__(THREADS) void classpass(const float* __restrict__ center) {
    __shared__ unsigned s_pack[CPB];   // (class << 14) | count   (count <= 16384)
    __shared__ int      s_m;
    __shared__ float    s_wsum[WPB];

    int tid  = threadIdx.x;
    int lane = tid & 31;
    int wid  = tid >> 5;

    if (tid == 0) s_m = 0;
    __syncthreads();

    int c0 = blockIdx.x * CPB + tid;
    if (c0 < NC) {
        int n = g_counts[c0];                  // coalesced 4B scan
        if (n > 0) {
            int p = atomicAdd(&s_m, 1);        // smem atomic: cheap
            s_pack[p] = ((unsigned)c0 << 14) | (unsigned)n;
        }
    }
    __syncthreads();

    int m = s_m;
    float acc = 0.f;

    for (int i = wid; i < m; i += WPB) {
        unsigned pk = s_pack[i];
        int   c  = (int)(pk >> 14);
        float n  = (float)(pk & 0x3FFFu);
        float bn = 0.01f / n;

        float4*       srow = g_sums + (size_t)c * F4;
        const float4* crow = reinterpret_cast<const float4*>(center) + (size_t)c * F4;

        float4 s0 = srow[lane], s1 = srow[lane + 32];
        float4 cv0 = crow[lane], cv1 = crow[lane + 32];

        // restore zero invariant
        float4 z = make_float4(0.f, 0.f, 0.f, 0.f);
        srow[lane] = z;
        srow[lane + 32] = z;

        #define TERM(cj, sj) { float t = fmaf(0.99f, (cj), bn * (sj)); \
                               acc += (fmaf(n, t, -2.f * (sj))) * t; }
        TERM(cv0.x, s0.x) TERM(cv0.y, s0.y) TERM(cv0.z, s0.z) TERM(cv0.w, s0.w)
        TERM(cv1.x, s1.x) TERM(cv1.y, s1.y) TERM(cv1.z, s1.z) TERM(cv1.w, s1.w)
        #undef TERM

        if (lane == 0) {
            acc += g_q[c];
            g_q[c]      = 0.f;     // restore invariants
            g_counts[c] = 0;
        }
    }

    #pragma unroll
    for (int o = 16; o > 0; o >>= 1)
        acc += __shfl_down_sync(0xFFFFFFFFu, acc, o);
    if (lane == 0) s_wsum[wid] = acc;
    __syncthreads();

    if (tid == 0) {
        float b = 0.f;
        #pragma unroll
        for (int i = 0; i < WPB; i++) b += s_wsum[i];
        g_partials[blockIdx.x] = b;
    }
}

// ---------------------------------------------------------------------------
// Pass 3: tiny deterministic reduce of 391 partials -> loss scalar.
// ---------------------------------------------------------------------------
__global__ __launch_bounds__(THREADS) void finalize(float* __restrict__ out) {
    __shared__ float sh[THREADS];
    float a = 0.f;
    for (int i = threadIdx.x; i < CLS_BLOCKS; i += THREADS)
        a += g_partials[i];
    sh[threadIdx.x] = a;
    __syncthreads();
    #pragma unroll
    for (int o = THREADS / 2; o > 0; o >>= 1) {
        if (threadIdx.x < o) sh[threadIdx.x] += sh[threadIdx.x + o];
        __syncthreads();
    }
    if (threadIdx.x == 0)
        out[0] = sh[0] * (1.f / ((float)BATCH * (float)FEAT));
}

extern "C" void kernel_launch(void* const* d_in, const int* in_sizes, int n_in,
                              void* d_out, int out_size) {
    const float* x      = (const float*)d_in[0];   // batch_feature [16384, 256] f32
    const int*   label  = (const int*)d_in[1];     // batch_label   [16384] int32
    const float* center = (const float*)d_in[2];   // center_feature[100000, 256] f32
    float* out = (float*)d_out;

    accum    <<<ACC_BLOCKS, THREADS>>>(x, label);
    classpass<<<CLS_BLOCKS, THREADS>>>(center);
    finalize <<<1, THREADS>>>(out);
}

// round 5
// speedup vs baseline: 4.9387x; 3.5711x over previous
#include <cuda_runtime.h>
#include <cstdint>

#define NC         100000
#define FEAT       256
#define BATCH      16384
#define F4         64                          // FEAT / 4
#define THREADS    256
#define WPB        8
#define CNT_BLOCKS (BATCH / THREADS)           // 64
#define ACC_BLOCKS (BATCH / WPB)               // 2048 (one warp per sample)
#define CPB        256                         // classes scanned per block
#define CLS_BLOCKS ((NC + CPB - 1) / CPB)      // 391
#define PARTIALS   512

// Coefficients from expanding ||x_i - t||^2 with t = 0.99 c + (0.01/n) s:
//   contrib_c = Q - 1.9602 D + 0.9801 E - (0.0199/n) ||s||^2
//   Q = sum ||x_i||^2, D = sum x_i.c = c.s, E = n ||c||^2
#define A_D 1.9602f
#define A_E 0.9801f
#define A_S 0.0199f

// Scratch — zero at module load; every replay restores the all-zero invariant.
__device__ float4 g_scal[NC];                  // {Q, D, E, n}  (1.6 MB)
__device__ float4 g_sums[(size_t)NC * F4];     // rows written ONLY for n>=2 classes
__device__ float  g_partials[PARTIALS];

__device__ __forceinline__ void red_add_v4(float* addr, float4 v) {
    asm volatile("red.global.add.v4.f32 [%0], {%1, %2, %3, %4};"
                 :: "l"(addr), "f"(v.x), "f"(v.y), "f"(v.z), "f"(v.w)
                 : "memory");
}

// ---------------------------------------------------------------------------
// Pass 0: per-class counts (float, exact below 2^24). Spread atomics, tiny.
// ---------------------------------------------------------------------------
__global__ __launch_bounds__(THREADS) void countk(const int* __restrict__ label) {
    int i = blockIdx.x * THREADS + threadIdx.x;
    atomicAdd(&g_scal[label[i]].w, 1.0f);
}

// ---------------------------------------------------------------------------
// Pass 1: one warp per sample. Read x row + center row, warp-reduce the three
// scalars, RED them into g_scal; RED the x row into g_sums only when n>=2.
// ---------------------------------------------------------------------------
__global__ __launch_bounds__(THREADS) void accum(const float* __restrict__ x,
                                                 const float* __restrict__ center,
                                                 const int* __restrict__ label) {
    int w    = (blockIdx.x * THREADS + threadIdx.x) >> 5;   // sample id
    int lane = threadIdx.x & 31;
    int c    = label[w];                                    // broadcast load

    const float4* xr = reinterpret_cast<const float4*>(x)      + (size_t)w * F4;
    const float4* cr = reinterpret_cast<const float4*>(center) + (size_t)c * F4;
    float4 v0 = xr[lane], v1 = xr[lane + 32];
    float4 c0 = cr[lane], c1 = cr[lane + 32];

    float q = v0.x*v0.x + v0.y*v0.y + v0.z*v0.z + v0.w*v0.w
            + v1.x*v1.x + v1.y*v1.y + v1.z*v1.z + v1.w*v1.w;
    float d = v0.x*c0.x + v0.y*c0.y + v0.z*c0.z + v0.w*c0.w
            + v1.x*c1.x + v1.y*c1.y + v1.z*c1.z + v1.w*c1.w;
    float e = c0.x*c0.x + c0.y*c0.y + c0.z*c0.z + c0.w*c0.w
            + c1.x*c1.x + c1.y*c1.y + c1.z*c1.z + c1.w*c1.w;

    #pragma unroll
    for (int o = 16; o > 0; o >>= 1) {
        q += __shfl_down_sync(0xFFFFFFFFu, q, o);
        d += __shfl_down_sync(0xFFFFFFFFu, d, o);
        e += __shfl_down_sync(0xFFFFFFFFu, e, o);
    }

    float n = g_scal[c].w;          // written by pass 0; broadcast load
    if (n >= 2.f) {                 // vector sum needed only for multi classes
        float* srow = reinterpret_cast<float*>(g_sums + (size_t)c * F4);
        red_add_v4(srow + lane * 4,        v0);
        red_add_v4(srow + (lane + 32) * 4, v1);
    }
    if (lane == 0) {
        atomicAdd(&g_scal[c].x, q);
        atomicAdd(&g_scal[c].y, d);
        atomicAdd(&g_scal[c].z, e);
    }
}

// ---------------------------------------------------------------------------
// Pass 2: coalesced scan of g_scal (16B/class). Scalar contribution per
// touched class; multi classes (n>=2) queue for a warp stage that reads the
// sums row, reduces ||s||^2 and zeroes it. All invariants restored here.
// ---------------------------------------------------------------------------
__global__ __launch_bounds__(THREADS) void classpass() {
    __shared__ int   s_m;
    __shared__ int   s_cls[CPB];
    __shared__ float s_n[CPB];
    __shared__ float s_wsum[WPB];

    int tid  = threadIdx.x;
    int lane = tid & 31;
    int wid  = tid >> 5;

    if (tid == 0) s_m = 0;
    __syncthreads();

    float contrib = 0.f;
    int c = blockIdx.x * CPB + tid;
    if (c < NC) {
        float4 sc = g_scal[c];                 // coalesced 16B
        if (sc.w > 0.f) {
            contrib = sc.x - A_D * sc.y + A_E * sc.z;
            if (sc.w == 1.f) {
                contrib -= A_S * sc.x;         // ||s||^2 == Q for n = 1
            } else {
                int p = atomicAdd(&s_m, 1);
                s_cls[p] = c;
                s_n[p]   = sc.w;
            }
            g_scal[c] = make_float4(0.f, 0.f, 0.f, 0.f);   // restore invariant
        }
    }
    __syncthreads();

    int m = s_m;                               // expected ~3 per block
    for (int i = wid; i < m; i += WPB) {
        int    cc = s_cls[i];
        float4* srow = g_sums + (size_t)cc * F4;
        float4 s0 = srow[lane], s1 = srow[lane + 32];
        float4 z = make_float4(0.f, 0.f, 0.f, 0.f);
        srow[lane] = z;                        // restore invariant
        srow[lane + 32] = z;
        float ss = s0.x*s0.x + s0.y*s0.y + s0.z*s0.z + s0.w*s0.w
                 + s1.x*s1.x + s1.y*s1.y + s1.z*s1.z + s1.w*s1.w;
        #pragma unroll
        for (int o = 16; o > 0; o >>= 1)
            ss += __shfl_down_sync(0xFFFFFFFFu, ss, o);
        if (lane == 0) contrib -= A_S * ss / s_n[i];
    }

    #pragma unroll
    for (int o = 16; o > 0; o >>= 1)
        contrib += __shfl_down_sync(0xFFFFFFFFu, contrib, o);
    if (lane == 0) s_wsum[wid] = contrib;
    __syncthreads();

    if (tid == 0) {
        float b = 0.f;
        #pragma unroll
        for (int i = 0; i < WPB; i++) b += s_wsum[i];
        g_partials[blockIdx.x] = b;
    }
}

// ---------------------------------------------------------------------------
// Pass 3: tiny deterministic reduce of 391 partials -> loss scalar.
// ---------------------------------------------------------------------------
__global__ __launch_bounds__(THREADS) void finalize(float* __restrict__ out) {
    __shared__ float sh[THREADS];
    float a = 0.f;
    for (int i = threadIdx.x; i < CLS_BLOCKS; i += THREADS)
        a += g_partials[i];
    sh[threadIdx.x] = a;
    __syncthreads();
    #pragma unroll
    for (int o = THREADS / 2; o > 0; o >>= 1) {
        if (threadIdx.x < o) sh[threadIdx.x] += sh[threadIdx.x + o];
        __syncthreads();
    }
    if (threadIdx.x == 0)
        out[0] = sh[0] * (1.f / ((float)BATCH * (float)FEAT));
}

extern "C" void kernel_launch(void* const* d_in, const int* in_sizes, int n_in,
                              void* d_out, int out_size) {
    const float* x      = (const float*)d_in[0];   // batch_feature [16384, 256] f32
    const int*   label  = (const int*)d_in[1];     // batch_label   [16384] int32
    const float* center = (const float*)d_in[2];   // center_feature[100000, 256] f32
    float* out = (float*)d_out;

    countk   <<<CNT_BLOCKS, THREADS>>>(label);
    accum    <<<ACC_BLOCKS, THREADS>>>(x, center, label);
    classpass<<<CLS_BLOCKS, THREADS>>>();
    finalize <<<1, THREADS>>>(out);
}